// round 9
// baseline (speedup 1.0000x reference)
#include <cuda_runtime.h>

#define T_DIM  128
#define C_IN   16
#define H_DIM  64
#define W_DIM  64
#define C_OUT  64

// Conv scratch [T+4, C_OUT, H, W]; +4 zero pad slices so the scan can prefetch
// depth-4 unconditionally (pads never written -> stay zero). ~138 MB scratch.
__device__ float g_conv[(size_t)(T_DIM + 4) * C_OUT * H_DIM * W_DIM];
// Transposed weights: [r = ci*9+kh*3+kw][c_out]  (natural c_out float2 pairs)
__device__ float g_wpackT[144 * 64];

// Packed f32x2 FMA (full-rate fp32 on sm_103a; ptxas never auto-emits FFMA2)
#define FMA2(acc, xp, wp) \
    asm("fma.rn.f32x2 %0, %1, %2, %0;" : "+l"(acc) : "l"(xp), "l"(wp))
#define DUP2(d, v) \
    asm("mov.b64 %0, {%1, %1};" : "=l"(d) : "f"(v))

#define W_FLOATS    (144 * 64)                     // 9216 floats = 36864 B
#define XS_FLOATS   (16 * 4 * 68)                  // 4352 floats = 17408 B
#define SMEM_BYTES  ((W_FLOATS + XS_FLOATS) * 4)   // 54272 B -> 3 blocks/SM

// One-time weight transpose: OIHW -> [r][c]
__global__ void wpack_kernel(const float* __restrict__ Wt)
{
    int i = blockIdx.x * 256 + threadIdx.x;        // 0..9215
    float w = Wt[i];
    int c = i / 144;
    int r = i - c * 144;
    g_wpackT[r * 64 + c] = w;
}

// Block: 256 thr = 8 warps, covers 2 output rows x 64 cols x 64 c_out for ONE t.
// Warp wg owns c_out [8wg, 8wg+8) as 4 natural float2 pairs. Lane: rl = lane>>4
// row-in-pair, cl = lane&15 -> pixels p0=4cl .. p0+3 (P=4).
// x tile [16 ci][4 rows][68]: col i holds x[i-1] (1-float shift, zero halos).
// Grid: blockIdx.x = tb*32 + ry; t = 127 - tb  (REVERSED so the scan, which
// reads t ascending, finds the low-t slices still resident in L2).
__global__ void __launch_bounds__(256, 3)
conv3x3_kernel(const float* __restrict__ x,
               const float* __restrict__ bias)
{
    extern __shared__ float smem[];
    float* Ws = smem;                  // [144][64]
    float* xs = smem + W_FLOATS;       // [16][4][68]

    const int tid = threadIdx.x;
    const int t   = (T_DIM - 1) - (blockIdx.x >> 5);   // reversed t order
    const int ry  = blockIdx.x & 31;

    // ---- weights: conflict-free linear float4 copy from prepacked global ----
    {
        const float4* wp  = (const float4*)g_wpackT;
        float4*       wsm = (float4*)Ws;
#pragma unroll
        for (int k = 0; k < 9; k++)                // 2304 float4
            wsm[tid + k * 256] = wp[tid + k * 256];
    }

    // ---- x tile: rows 2ry-1..2ry+2, 16 ci, float4 gmem reads, +1 col shift ----
#pragma unroll
    for (int k = 0; k < 4; k++) {
        int i   = tid + k * 256;
        int ci  = i >> 6;
        int rem = i & 63;
        int rt  = rem >> 4;
        int w4  = rem & 15;
        int grow = 2 * ry + rt - 1;
        float4 v = make_float4(0.f, 0.f, 0.f, 0.f);
        if (grow >= 0 && grow < H_DIM)
            v = *(const float4*)(x + (((size_t)t * C_IN + ci) * H_DIM + grow) * W_DIM + 4 * w4);
        float* d = xs + (ci * 4 + rt) * 68 + 1 + 4 * w4;
        d[0] = v.x; d[1] = v.y; d[2] = v.z; d[3] = v.w;
    }
    // halo pads (cols 0,65,66,67 of each of 64 tile rows)
    if (tid < 64) {
        xs[tid * 68 + 0]  = 0.f;
        xs[tid * 68 + 65] = 0.f;
        xs[tid * 68 + 66] = 0.f;
        xs[tid * 68 + 67] = 0.f;
    }

    const int wg   = tid >> 5;
    const int lane = tid & 31;
    const int rl   = lane >> 4;
    const int cl   = lane & 15;
    const int p0   = 4 * cl;               // first pixel col
    const int c0   = wg * 8;               // c_out base (4 pairs)

    // bias pairs
    unsigned long long bp[4];
#pragma unroll
    for (int j = 0; j < 4; j++) {
        float2 bb = *(const float2*)(bias + c0 + 2 * j);
        asm("mov.b64 %0, {%1, %2};" : "=l"(bp[j]) : "f"(bb.x), "f"(bb.y));
    }
    __syncthreads();

    // acc[j][px]: c_out pair j (c0+2j, c0+2j+1), pixel p0+px
    unsigned long long acc[4][4];
#pragma unroll
    for (int j = 0; j < 4; j++) {
        acc[j][0] = bp[j]; acc[j][1] = bp[j];
        acc[j][2] = bp[j]; acc[j][3] = bp[j];
    }

    const float* xwarp = xs + rl * 68 + p0;          // + (ci*4+kh)*68
#pragma unroll 1
    for (int ci = 0; ci < C_IN; ci++) {
#pragma unroll
        for (int kh = 0; kh < 3; kh++) {
            // x[p0-1 .. p0+4] at smem idx p0..p0+5 : LDS.128 + LDS.64 (aligned)
            const float* xr = xwarp + (ci * 4 + kh) * 68;
            float4 q  = *(const float4*)xr;
            float2 q2 = *(const float2*)(xr + 4);
            unsigned long long xd[6];
            DUP2(xd[0], q.x);  DUP2(xd[1], q.y);  DUP2(xd[2], q.z);
            DUP2(xd[3], q.w);  DUP2(xd[4], q2.x); DUP2(xd[5], q2.y);

            const float* wb = Ws + (ci * 9 + kh * 3) * 64 + c0;
#pragma unroll
            for (int kw = 0; kw < 3; kw++) {
                // 4 c_out pairs, warp-uniform broadcast (2x LDS.128)
                const ulonglong2* wq = (const ulonglong2*)(wb + kw * 64);
                ulonglong2 u0 = wq[0], u1 = wq[1];
                FMA2(acc[0][0], xd[kw+0], u0.x); FMA2(acc[0][1], xd[kw+1], u0.x);
                FMA2(acc[0][2], xd[kw+2], u0.x); FMA2(acc[0][3], xd[kw+3], u0.x);
                FMA2(acc[1][0], xd[kw+0], u0.y); FMA2(acc[1][1], xd[kw+1], u0.y);
                FMA2(acc[1][2], xd[kw+2], u0.y); FMA2(acc[1][3], xd[kw+3], u0.y);
                FMA2(acc[2][0], xd[kw+0], u1.x); FMA2(acc[2][1], xd[kw+1], u1.x);
                FMA2(acc[2][2], xd[kw+2], u1.x); FMA2(acc[2][3], xd[kw+3], u1.x);
                FMA2(acc[3][0], xd[kw+0], u1.y); FMA2(acc[3][1], xd[kw+1], u1.y);
                FMA2(acc[3][2], xd[kw+2], u1.y); FMA2(acc[3][3], xd[kw+3], u1.y);
            }
        }
    }

    // ---- epilogue: regroup -> per-c_out float4 stores (256B warp runs) ----
    const int row = 2 * ry + rl;
    float* op = g_conv + (((size_t)t * C_OUT + c0) * H_DIM + row) * W_DIM + p0;
#pragma unroll
    for (int j = 0; j < 4; j++) {
        float a0, b0, a1, b1, a2, b2, a3, b3;   // aX = c0+2j, bX = c0+2j+1
        asm("mov.b64 {%0,%1}, %2;" : "=f"(a0), "=f"(b0) : "l"(acc[j][0]));
        asm("mov.b64 {%0,%1}, %2;" : "=f"(a1), "=f"(b1) : "l"(acc[j][1]));
        asm("mov.b64 {%0,%1}, %2;" : "=f"(a2), "=f"(b2) : "l"(acc[j][2]));
        asm("mov.b64 {%0,%1}, %2;" : "=f"(a3), "=f"(b3) : "l"(acc[j][3]));
        *(float4*)(op + (size_t)(2 * j)     * H_DIM * W_DIM) = make_float4(a0, a1, a2, a3);
        *(float4*)(op + (size_t)(2 * j + 1) * H_DIM * W_DIM) = make_float4(b0, b1, b2, b3);
    }
}

// LIF scan over T per element. Scalar, 262144 threads, depth-4 prefetch.
// g_conv reads use default caching (low-t slices are L2-resident thanks to the
// conv's reversed t order); spike stores use __stcs (evict-first) so the output
// write stream doesn't purge the cached conv data.
__global__ void __launch_bounds__(256)
lif_scan_kernel(float* __restrict__ out)
{
    const int idx = blockIdx.x * 256 + threadIdx.x;        // 0..262143
    const float* __restrict__ cv = (const float*)g_conv;
    const size_t N = 262144;

    float s  = 0.f;
    float c0 = cv[idx];
    float c1 = cv[N + idx];
    float c2 = cv[2 * N + idx];
    float c3 = cv[3 * N + idx];
#pragma unroll 4
    for (int t = 0; t < T_DIM; t++) {
        float cn = cv[(size_t)(t + 4) * N + idx];          // prefetch (pads ok)
        s += c0;
        float sp = (s >= 8.f) ? 1.f : 0.f;
        s = (s >= 8.f) ? 0.f : fmaxf(s, -1.f);
        __stcs(out + (size_t)t * N + idx, sp);             // streaming store
        c0 = c1; c1 = c2; c2 = c3; c3 = cn;
    }
}

extern "C" void kernel_launch(void* const* d_in, const int* in_sizes, int n_in,
                              void* d_out, int out_size)
{
    const float* x  = (const float*)d_in[0];   // [128,16,64,64]
    const float* Wt = (const float*)d_in[1];   // [64,16,3,3]
    const float* b  = (const float*)d_in[2];   // [64]
    float* out = (float*)d_out;                // [128,64,64,64]

    cudaFuncSetAttribute(conv3x3_kernel,
                         cudaFuncAttributeMaxDynamicSharedMemorySize, SMEM_BYTES);

    wpack_kernel<<<36, 256>>>(Wt);
    conv3x3_kernel<<<T_DIM * 32, 256, SMEM_BYTES>>>(x, b);   // 4096 blocks
    lif_scan_kernel<<<1024, 256>>>(out);
}

// round 12
// speedup vs baseline: 1.2075x; 1.2075x over previous
#include <cuda_runtime.h>

#define T_DIM  128
#define C_IN   16
#define H_DIM  64
#define W_DIM  64
#define C_OUT  64

// Conv scratch [T+3, C_OUT, H, W]; +3 zero pad slices so the scan can prefetch
// depth-3 unconditionally (pads never written -> stay zero). ~137 MB scratch.
__device__ float g_conv[(size_t)(T_DIM + 3) * C_OUT * H_DIM * W_DIM];

// Packed f32x2 FMA (full-rate fp32 on sm_103a; ptxas never auto-emits FFMA2)
#define FMA2(acc, xp, wp) \
    asm("fma.rn.f32x2 %0, %1, %2, %0;" : "+l"(acc) : "l"(xp), "l"(wp))
#define DUP2(d, v) \
    asm("mov.b64 %0, {%1, %1};" : "=l"(d) : "f"(v))

#define W_FLOATS    (144 * 64)                     // 9216 floats = 36864 B
#define XS_FLOATS   (16 * 4 * 68)                  // 4352 floats = 17408 B
#define SMEM_BYTES  ((W_FLOATS + XS_FLOATS) * 4)   // 54272 B -> 3 blocks/SM

// Block: 256 thr = 8 warps, covers 2 output rows x 64 cols x 64 c_out for ONE t.
// Warp wg owns c_out [8wg, 8wg+8) as 4 natural float2 pairs. Lane: rl = lane>>4
// row-in-pair, cl = lane&15 -> pixels p0=4cl .. p0+3 (P=4).
// x tile [16 ci][4 rows][68]: col i holds x[i-1] (1-float shift, zero halos).
// Grid: blockIdx.x = t*32 + ry; output rows 2ry, 2ry+1. Forward t order.
__global__ void __launch_bounds__(256, 3)
conv3x3_kernel(const float* __restrict__ x,
               const float* __restrict__ Wt,
               const float* __restrict__ bias)
{
    extern __shared__ float smem[];
    float* Ws = smem;                  // [144][64]  (r = ci*9+kh*3+kw, c = c_out)
    float* xs = smem + W_FLOATS;       // [16][4][68]

    const int tid = threadIdx.x;
    const int t   = blockIdx.x >> 5;
    const int ry  = blockIdx.x & 31;

    // ---- weights: direct transposed fill from Wt (OIHW). Lanes map to
    // consecutive c -> STS banks all distinct (conflict-free); LDG is a
    // stride-144B gather (L2-hot after wave 1), pure LSU work that overlaps
    // other blocks' FFMA2. Replaces the separate wpack kernel (-4.5us serial).
#pragma unroll
    for (int k = 0; k < 36; k++) {
        int i = tid + k * 256;         // 0..9215
        int c = i & 63;                // c_out
        int r = i >> 6;                // ci*9 + kh*3 + kw
        Ws[r * 64 + c] = Wt[c * 144 + r];
    }

    // ---- x tile: rows 2ry-1..2ry+2, 16 ci, float4 gmem reads, +1 col shift ----
#pragma unroll
    for (int k = 0; k < 4; k++) {
        int i   = tid + k * 256;
        int ci  = i >> 6;
        int rem = i & 63;
        int rt  = rem >> 4;
        int w4  = rem & 15;
        int grow = 2 * ry + rt - 1;
        float4 v = make_float4(0.f, 0.f, 0.f, 0.f);
        if (grow >= 0 && grow < H_DIM)
            v = *(const float4*)(x + (((size_t)t * C_IN + ci) * H_DIM + grow) * W_DIM + 4 * w4);
        float* d = xs + (ci * 4 + rt) * 68 + 1 + 4 * w4;
        d[0] = v.x; d[1] = v.y; d[2] = v.z; d[3] = v.w;
    }
    // halo pads (cols 0,65,66,67 of each of 64 tile rows)
    if (tid < 64) {
        xs[tid * 68 + 0]  = 0.f;
        xs[tid * 68 + 65] = 0.f;
        xs[tid * 68 + 66] = 0.f;
        xs[tid * 68 + 67] = 0.f;
    }

    const int wg   = tid >> 5;
    const int lane = tid & 31;
    const int rl   = lane >> 4;
    const int cl   = lane & 15;
    const int p0   = 4 * cl;               // first pixel col
    const int c0   = wg * 8;               // c_out base (4 pairs)

    // bias pairs
    unsigned long long bp[4];
#pragma unroll
    for (int j = 0; j < 4; j++) {
        float2 bb = *(const float2*)(bias + c0 + 2 * j);
        asm("mov.b64 %0, {%1, %2};" : "=l"(bp[j]) : "f"(bb.x), "f"(bb.y));
    }
    __syncthreads();

    // acc[j][px]: c_out pair j (c0+2j, c0+2j+1), pixel p0+px
    unsigned long long acc[4][4];
#pragma unroll
    for (int j = 0; j < 4; j++) {
        acc[j][0] = bp[j]; acc[j][1] = bp[j];
        acc[j][2] = bp[j]; acc[j][3] = bp[j];
    }

    const float* xwarp = xs + rl * 68 + p0;          // + (ci*4+kh)*68
#pragma unroll 1
    for (int ci = 0; ci < C_IN; ci++) {
#pragma unroll
        for (int kh = 0; kh < 3; kh++) {
            // x[p0-1 .. p0+4] at smem idx p0..p0+5 : LDS.128 + LDS.64 (aligned)
            const float* xr = xwarp + (ci * 4 + kh) * 68;
            float4 q  = *(const float4*)xr;
            float2 q2 = *(const float2*)(xr + 4);
            unsigned long long xd[6];
            DUP2(xd[0], q.x);  DUP2(xd[1], q.y);  DUP2(xd[2], q.z);
            DUP2(xd[3], q.w);  DUP2(xd[4], q2.x); DUP2(xd[5], q2.y);

            const float* wb = Ws + (ci * 9 + kh * 3) * 64 + c0;
#pragma unroll
            for (int kw = 0; kw < 3; kw++) {
                // 4 c_out pairs, warp-uniform broadcast (2x LDS.128)
                const ulonglong2* wq = (const ulonglong2*)(wb + kw * 64);
                ulonglong2 u0 = wq[0], u1 = wq[1];
                FMA2(acc[0][0], xd[kw+0], u0.x); FMA2(acc[0][1], xd[kw+1], u0.x);
                FMA2(acc[0][2], xd[kw+2], u0.x); FMA2(acc[0][3], xd[kw+3], u0.x);
                FMA2(acc[1][0], xd[kw+0], u0.y); FMA2(acc[1][1], xd[kw+1], u0.y);
                FMA2(acc[1][2], xd[kw+2], u0.y); FMA2(acc[1][3], xd[kw+3], u0.y);
                FMA2(acc[2][0], xd[kw+0], u1.x); FMA2(acc[2][1], xd[kw+1], u1.x);
                FMA2(acc[2][2], xd[kw+2], u1.x); FMA2(acc[2][3], xd[kw+3], u1.x);
                FMA2(acc[3][0], xd[kw+0], u1.y); FMA2(acc[3][1], xd[kw+1], u1.y);
                FMA2(acc[3][2], xd[kw+2], u1.y); FMA2(acc[3][3], xd[kw+3], u1.y);
            }
        }
    }

    // ---- epilogue: regroup -> per-c_out float4 stores (256B warp runs) ----
    const int row = 2 * ry + rl;
    float* op = g_conv + (((size_t)t * C_OUT + c0) * H_DIM + row) * W_DIM + p0;
#pragma unroll
    for (int j = 0; j < 4; j++) {
        float a0, b0, a1, b1, a2, b2, a3, b3;   // aX = c0+2j, bX = c0+2j+1
        asm("mov.b64 {%0,%1}, %2;" : "=f"(a0), "=f"(b0) : "l"(acc[j][0]));
        asm("mov.b64 {%0,%1}, %2;" : "=f"(a1), "=f"(b1) : "l"(acc[j][1]));
        asm("mov.b64 {%0,%1}, %2;" : "=f"(a2), "=f"(b2) : "l"(acc[j][2]));
        asm("mov.b64 {%0,%1}, %2;" : "=f"(a3), "=f"(b3) : "l"(acc[j][3]));
        *(float4*)(op + (size_t)(2 * j)     * H_DIM * W_DIM) = make_float4(a0, a1, a2, a3);
        *(float4*)(op + (size_t)(2 * j + 1) * H_DIM * W_DIM) = make_float4(b0, b1, b2, b3);
    }
}

// LIF scan over T per element. Scalar, 262144 threads, depth-3 prefetch
// (3 zero pad slices make t+3 reads always in-bounds). R8-exact.
__global__ void __launch_bounds__(256)
lif_scan_kernel(float* __restrict__ out)
{
    const int idx = blockIdx.x * 256 + threadIdx.x;        // 0..262143
    const float* __restrict__ cv = (const float*)g_conv;
    const size_t N = 262144;

    float s  = 0.f;
    float c0 = cv[idx];
    float c1 = cv[N + idx];
    float c2 = cv[2 * N + idx];
#pragma unroll 4
    for (int t = 0; t < T_DIM; t++) {
        float cn = cv[(size_t)(t + 3) * N + idx];          // prefetch (pads ok)
        s += c0;
        float sp = (s >= 8.f) ? 1.f : 0.f;
        s = (s >= 8.f) ? 0.f : fmaxf(s, -1.f);
        out[(size_t)t * N + idx] = sp;
        c0 = c1; c1 = c2; c2 = cn;
    }
}

extern "C" void kernel_launch(void* const* d_in, const int* in_sizes, int n_in,
                              void* d_out, int out_size)
{
    const float* x  = (const float*)d_in[0];   // [128,16,64,64]
    const float* Wt = (const float*)d_in[1];   // [64,16,3,3]
    const float* b  = (const float*)d_in[2];   // [64]
    float* out = (float*)d_out;                // [128,64,64,64]

    cudaFuncSetAttribute(conv3x3_kernel,
                         cudaFuncAttributeMaxDynamicSharedMemorySize, SMEM_BYTES);

    conv3x3_kernel<<<T_DIM * 32, 256, SMEM_BYTES>>>(x, Wt, b);   // 4096 blocks
    lif_scan_kernel<<<1024, 256>>>(out);
}

// round 13
// speedup vs baseline: 1.4985x; 1.2410x over previous
#include <cuda_runtime.h>

#define T_DIM  128
#define C_IN   16
#define H_DIM  64
#define W_DIM  64
#define C_OUT  64

// Conv scratch [T+8, C_OUT, H, W]; +8 zero pad slices so the scan can prefetch
// depth-8 unconditionally (pads never written -> stay zero). ~142 MB scratch.
__device__ float g_conv[(size_t)(T_DIM + 8) * C_OUT * H_DIM * W_DIM];
// Transposed weights: [r = ci*9+kh*3+kw][c_out]  (natural c_out float2 pairs)
__device__ float g_wpackT[144 * 64];

// Packed f32x2 FMA (full-rate fp32 on sm_103a; ptxas never auto-emits FFMA2)
#define FMA2(acc, xp, wp) \
    asm("fma.rn.f32x2 %0, %1, %2, %0;" : "+l"(acc) : "l"(xp), "l"(wp))
#define DUP2(d, v) \
    asm("mov.b64 %0, {%1, %1};" : "=l"(d) : "f"(v))

#define W_FLOATS    (144 * 64)                     // 9216 floats = 36864 B
#define XS_FLOATS   (16 * 4 * 68)                  // 4352 floats = 17408 B
#define SMEM_BYTES  ((W_FLOATS + XS_FLOATS) * 4)   // 54272 B -> 3 blocks/SM

// One-time weight transpose: OIHW -> [r][c]. Coalesced LDG, scattered STG —
// 4.5us total; vastly cheaper than any in-kernel transposed gather (R12 lesson).
__global__ void wpack_kernel(const float* __restrict__ Wt)
{
    int i = blockIdx.x * 256 + threadIdx.x;        // 0..9215
    float w = Wt[i];
    int c = i / 144;
    int r = i - c * 144;
    g_wpackT[r * 64 + c] = w;
}

// Block: 256 thr = 8 warps, covers 2 output rows x 64 cols x 64 c_out for ONE t.
// Warp wg owns c_out [8wg, 8wg+8) as 4 natural float2 pairs. Lane: rl = lane>>4
// row-in-pair, cl = lane&15 -> pixels p0=4cl .. p0+3 (P=4).
// x tile [16 ci][4 rows][68]: col i holds x[i-1] (1-float shift, zero halos).
// Grid: blockIdx.x = t*32 + ry; output rows 2ry, 2ry+1. Forward t order.
__global__ void __launch_bounds__(256, 3)
conv3x3_kernel(const float* __restrict__ x,
               const float* __restrict__ bias)
{
    extern __shared__ float smem[];
    float* Ws = smem;                  // [144][64]
    float* xs = smem + W_FLOATS;       // [16][4][68]

    const int tid = threadIdx.x;
    const int t   = blockIdx.x >> 5;
    const int ry  = blockIdx.x & 31;

    // ---- weights: conflict-free linear float4 copy from prepacked global ----
    {
        const float4* wp  = (const float4*)g_wpackT;
        float4*       wsm = (float4*)Ws;
#pragma unroll
        for (int k = 0; k < 9; k++)                // 2304 float4
            wsm[tid + k * 256] = wp[tid + k * 256];
    }

    // ---- x tile: rows 2ry-1..2ry+2, 16 ci, float4 gmem reads, +1 col shift ----
#pragma unroll
    for (int k = 0; k < 4; k++) {
        int i   = tid + k * 256;
        int ci  = i >> 6;
        int rem = i & 63;
        int rt  = rem >> 4;
        int w4  = rem & 15;
        int grow = 2 * ry + rt - 1;
        float4 v = make_float4(0.f, 0.f, 0.f, 0.f);
        if (grow >= 0 && grow < H_DIM)
            v = *(const float4*)(x + (((size_t)t * C_IN + ci) * H_DIM + grow) * W_DIM + 4 * w4);
        float* d = xs + (ci * 4 + rt) * 68 + 1 + 4 * w4;
        d[0] = v.x; d[1] = v.y; d[2] = v.z; d[3] = v.w;
    }
    // halo pads (cols 0,65,66,67 of each of 64 tile rows)
    if (tid < 64) {
        xs[tid * 68 + 0]  = 0.f;
        xs[tid * 68 + 65] = 0.f;
        xs[tid * 68 + 66] = 0.f;
        xs[tid * 68 + 67] = 0.f;
    }

    const int wg   = tid >> 5;
    const int lane = tid & 31;
    const int rl   = lane >> 4;
    const int cl   = lane & 15;
    const int p0   = 4 * cl;               // first pixel col
    const int c0   = wg * 8;               // c_out base (4 pairs)

    // bias pairs
    unsigned long long bp[4];
#pragma unroll
    for (int j = 0; j < 4; j++) {
        float2 bb = *(const float2*)(bias + c0 + 2 * j);
        asm("mov.b64 %0, {%1, %2};" : "=l"(bp[j]) : "f"(bb.x), "f"(bb.y));
    }
    __syncthreads();

    // acc[j][px]: c_out pair j (c0+2j, c0+2j+1), pixel p0+px
    unsigned long long acc[4][4];
#pragma unroll
    for (int j = 0; j < 4; j++) {
        acc[j][0] = bp[j]; acc[j][1] = bp[j];
        acc[j][2] = bp[j]; acc[j][3] = bp[j];
    }

    const float* xwarp = xs + rl * 68 + p0;          // + (ci*4+kh)*68
#pragma unroll 1
    for (int ci = 0; ci < C_IN; ci++) {
#pragma unroll
        for (int kh = 0; kh < 3; kh++) {
            // x[p0-1 .. p0+4] at smem idx p0..p0+5 : LDS.128 + LDS.64 (aligned)
            const float* xr = xwarp + (ci * 4 + kh) * 68;
            float4 q  = *(const float4*)xr;
            float2 q2 = *(const float2*)(xr + 4);
            unsigned long long xd[6];
            DUP2(xd[0], q.x);  DUP2(xd[1], q.y);  DUP2(xd[2], q.z);
            DUP2(xd[3], q.w);  DUP2(xd[4], q2.x); DUP2(xd[5], q2.y);

            const float* wb = Ws + (ci * 9 + kh * 3) * 64 + c0;
#pragma unroll
            for (int kw = 0; kw < 3; kw++) {
                // 4 c_out pairs, warp-uniform broadcast (2x LDS.128)
                const ulonglong2* wq = (const ulonglong2*)(wb + kw * 64);
                ulonglong2 u0 = wq[0], u1 = wq[1];
                FMA2(acc[0][0], xd[kw+0], u0.x); FMA2(acc[0][1], xd[kw+1], u0.x);
                FMA2(acc[0][2], xd[kw+2], u0.x); FMA2(acc[0][3], xd[kw+3], u0.x);
                FMA2(acc[1][0], xd[kw+0], u0.y); FMA2(acc[1][1], xd[kw+1], u0.y);
                FMA2(acc[1][2], xd[kw+2], u0.y); FMA2(acc[1][3], xd[kw+3], u0.y);
                FMA2(acc[2][0], xd[kw+0], u1.x); FMA2(acc[2][1], xd[kw+1], u1.x);
                FMA2(acc[2][2], xd[kw+2], u1.x); FMA2(acc[2][3], xd[kw+3], u1.x);
                FMA2(acc[3][0], xd[kw+0], u1.y); FMA2(acc[3][1], xd[kw+1], u1.y);
                FMA2(acc[3][2], xd[kw+2], u1.y); FMA2(acc[3][3], xd[kw+3], u1.y);
            }
        }
    }

    // ---- epilogue: regroup -> per-c_out float4 stores (256B warp runs) ----
    const int row = 2 * ry + rl;
    float* op = g_conv + (((size_t)t * C_OUT + c0) * H_DIM + row) * W_DIM + p0;
#pragma unroll
    for (int j = 0; j < 4; j++) {
        float a0, b0, a1, b1, a2, b2, a3, b3;   // aX = c0+2j, bX = c0+2j+1
        asm("mov.b64 {%0,%1}, %2;" : "=f"(a0), "=f"(b0) : "l"(acc[j][0]));
        asm("mov.b64 {%0,%1}, %2;" : "=f"(a1), "=f"(b1) : "l"(acc[j][1]));
        asm("mov.b64 {%0,%1}, %2;" : "=f"(a2), "=f"(b2) : "l"(acc[j][2]));
        asm("mov.b64 {%0,%1}, %2;" : "=f"(a3), "=f"(b3) : "l"(acc[j][3]));
        *(float4*)(op + (size_t)(2 * j)     * H_DIM * W_DIM) = make_float4(a0, a1, a2, a3);
        *(float4*)(op + (size_t)(2 * j + 1) * H_DIM * W_DIM) = make_float4(b0, b1, b2, b3);
    }
}

// LIF scan over T per element. Scalar, 262144 threads, depth-8 prefetch ring
// (8 zero pad slices keep t+8 reads in-bounds). Full unroll-8 makes the ring
// index t&7 static per copy: no shift movs, 8 independent loads batch per
// group -> ~8.4 MB in flight (vs 3.0 MB needed at 8 TB/s x ~380 ns).
__global__ void __launch_bounds__(256)
lif_scan_kernel(float* __restrict__ out)
{
    const int idx = blockIdx.x * 256 + threadIdx.x;        // 0..262143
    const float* __restrict__ cv = (const float*)g_conv;
    const size_t N = 262144;

    float c[8];
#pragma unroll
    for (int k = 0; k < 8; k++) c[k] = cv[(size_t)k * N + idx];

    float s = 0.f;
#pragma unroll 8
    for (int t = 0; t < T_DIM; t++) {
        float cur = c[t & 7];
        c[t & 7] = cv[(size_t)(t + 8) * N + idx];          // prefetch (pads ok)
        s += cur;
        float sp = (s >= 8.f) ? 1.f : 0.f;
        s = (s >= 8.f) ? 0.f : fmaxf(s, -1.f);
        out[(size_t)t * N + idx] = sp;
    }
}

extern "C" void kernel_launch(void* const* d_in, const int* in_sizes, int n_in,
                              void* d_out, int out_size)
{
    const float* x  = (const float*)d_in[0];   // [128,16,64,64]
    const float* Wt = (const float*)d_in[1];   // [64,16,3,3]
    const float* b  = (const float*)d_in[2];   // [64]
    float* out = (float*)d_out;                // [128,64,64,64]

    cudaFuncSetAttribute(conv3x3_kernel,
                         cudaFuncAttributeMaxDynamicSharedMemorySize, SMEM_BYTES);

    wpack_kernel<<<36, 256>>>(Wt);
    conv3x3_kernel<<<T_DIM * 32, 256, SMEM_BYTES>>>(x, b);   // 4096 blocks
    lif_scan_kernel<<<1024, 256>>>(out);
}